// round 13
// baseline (speedup 1.0000x reference)
#include <cuda_runtime.h>
#include <cuda_fp16.h>
#include <cstdint>
#include <math.h>

#define T_TOTAL 65536
#define T_BATCH 8192
#define CH 256
#define MEL 640

// ---------------- scratch (__device__ globals) ------------------------------
__device__ float  g_h[(size_t)T_TOTAL * CH];       // fp32 residual
__device__ float  g_skip[(size_t)T_TOTAL * CH];    // fp32 skip accumulator
__device__ __half g_hH[(size_t)T_TOTAL * CH];      // fp16 shadow of h
__device__ __half g_actsH[(size_t)T_TOTAL * CH];   // fp16 activations
__device__ __half g_spectH[(size_t)T_TOTAL * MEL]; // fp16 spect
__device__ __half g_wA[(size_t)8 * 512 * 1408];    // [layer][n][k]
__device__ __half g_wB[(size_t)7 * 512 * 256];     // [layer][n][k]
__device__ __half g_wL[(size_t)256 * 256];         // [n][k]

// ---------------- helpers ---------------------------------------------------
__device__ __forceinline__ uint32_t smem_u32(const void* p) {
    uint32_t a;
    asm("{ .reg .u64 t; cvta.to.shared.u64 t, %1; cvt.u32.u64 %0, t; }" : "=r"(a) : "l"(p));
    return a;
}

#define CP16(dst, src, sz) \
    asm volatile("cp.async.cg.shared.global [%0], [%1], 16, %2;" \
        :: "r"(dst), "l"(src), "r"(sz) : "memory")
#define CP_COMMIT() asm volatile("cp.async.commit_group;" ::: "memory")
#define CP_WAIT(n)  asm volatile("cp.async.wait_group %0;" :: "n"(n) : "memory")

__device__ __forceinline__ void mma16(float* d, const uint32_t* a, const uint32_t* b) {
    asm volatile(
        "mma.sync.aligned.m16n8k16.row.col.f32.f16.f16.f32 "
        "{%0,%1,%2,%3}, {%4,%5,%6,%7}, {%8,%9}, {%0,%1,%2,%3};"
        : "+f"(d[0]), "+f"(d[1]), "+f"(d[2]), "+f"(d[3])
        : "r"(a[0]), "r"(a[1]), "r"(a[2]), "r"(a[3]), "r"(b[0]), "r"(b[1]));
}

__device__ __forceinline__ void ldm4(uint32_t* r, uint32_t addr) {
    asm volatile("ldmatrix.sync.aligned.m8n8.x4.shared.b16 {%0,%1,%2,%3}, [%4];"
        : "=r"(r[0]), "=r"(r[1]), "=r"(r[2]), "=r"(r[3]) : "r"(addr));
}

#define HST 72   // smem row stride in halves (64 data + 8 pad = 144 B)

// ---- layerA/B layout: A 128 rows x 144B, B 128 rows x 144B -----------------
#define OFF_A(buf) ((buf) * 36864)
#define OFF_B(buf) (18432 + (buf) * 36864)
#define OFF_BIAS   73728
#define SMEM_AB    75776
// ---- layerL: A 128 rows, B 64 rows ------------------------------------------
#define OFFL_A(buf) ((buf) * 27648)
#define OFFL_B(buf) (18432 + (buf) * 27648)
#define OFFL_BIAS   55296
#define SMEM_L      56320

// ---------------------------------------------------------------------------
// prepW: all weights -> [n][k] fp16 (single launch)
// ---------------------------------------------------------------------------
#define NA (8u * 512u * 1408u)
#define NB (7u * 512u * 256u)
#define NL (256u * 256u)
__global__ void prepW_kernel(const float* __restrict__ in_w,
                             const float* __restrict__ cond_w,
                             const float* __restrict__ rsw,
                             const float* __restrict__ rlw) {
    uint32_t idx = blockIdx.x * blockDim.x + threadIdx.x;
    if (idx < NA) {
        int k = (int)(idx % 1408u);
        uint32_t t = idx / 1408u;
        int n = (int)(t & 511u);
        int l = (int)(t >> 9);
        float v;
        if (k < 768)
            v = in_w[(((size_t)l * 3 + (k >> 8)) * 256 + (k & 255)) * 512 + n];
        else
            v = cond_w[((size_t)l * 640 + (k - 768)) * 512 + n];
        g_wA[idx] = __float2half_rn(v);
    } else if (idx < NA + NB) {
        uint32_t r = idx - NA;
        int k = (int)(r & 255u);
        uint32_t t = r >> 8;
        int n = (int)(t & 511u);
        int l = (int)(t >> 9);
        g_wB[r] = __float2half_rn(rsw[((size_t)l * 256 + k) * 512 + n]);
    } else if (idx < NA + NB + NL) {
        uint32_t r = idx - NA - NB;
        int k = (int)(r & 255u);
        int n = (int)(r >> 8);
        g_wL[r] = __float2half_rn(rlw[k * 256 + n]);
    }
}

// ---------------------------------------------------------------------------
// start: h = audio @ start_w + start_b ; hH = fp16(h); skip = 0
// ---------------------------------------------------------------------------
__global__ void start_kernel(const float* __restrict__ audio,
                             const float* __restrict__ sw,
                             const float* __restrict__ sb) {
    int idx = blockIdx.x * blockDim.x + threadIdx.x;
    int t = idx >> 8;
    int c = idx & 255;
    float4 a = *(const float4*)&audio[(size_t)t * 4];
    float v = sb[c] + a.x * sw[c] + a.y * sw[256 + c] + a.z * sw[512 + c] + a.w * sw[768 + c];
    g_h[idx] = v;
    g_hH[idx] = __float2half_rn(v);
    g_skip[idx] = 0.f;
}

__global__ void prepS_kernel(const float* __restrict__ spect) {
    size_t idx = (size_t)blockIdx.x * blockDim.x + threadIdx.x;
    g_spectH[idx] = __float2half_rn(spect[idx]);
}

// ---------------------------------------------------------------------------
// fp16 compute via ldmatrix: warp 32(M) x 32(N) per half; BK=64 (4 k16 steps)
// abuf/bbuf are smem BYTE addresses of the A/B tiles.
// A x4: lanes0-15 -> rows mb+(lane&15) @k0 ; lanes16-31 -> same rows @k0+8
// B x4: lanes0-7 rows0-7@k0, 8-15 rows0-7@k0+8, 16-23 rows8-15@k0, 24-31 rows8-15@k0+8
//   => r0,r1 = b frag of n-block 0 ; r2,r3 = n-block 1
// ---------------------------------------------------------------------------
__device__ __forceinline__ void compute_f16(uint32_t abuf, uint32_t bbuf,
                                            int wm, int wn, int lane,
                                            float d[2][2][4][4], int nhalves) {
    const uint32_t a_off = abuf + ((wm * 32 + (lane & 15)) * HST + (lane >> 4) * 8) * 2;
    const uint32_t b_off = bbuf + ((wn * 32 + (lane & 7) + (lane >> 4) * 8) * HST
                                   + ((lane >> 3) & 1) * 8) * 2;
    #pragma unroll
    for (int q = 0; q < 4; q++) {
        uint32_t a[2][4];
        ldm4(a[0], a_off + q * 32);
        ldm4(a[1], a_off + 16 * HST * 2 + q * 32);
        #pragma unroll
        for (int t = 0; t < 2; t++) {
            if (t >= nhalves) break;
            #pragma unroll
            for (int nq = 0; nq < 2; nq++) {
                uint32_t b[4];
                ldm4(b, b_off + (t * 64 + nq * 16) * HST * 2 + q * 32);
                mma16(d[t][0][nq * 2],     a[0], b);
                mma16(d[t][1][nq * 2],     a[1], b);
                mma16(d[t][0][nq * 2 + 1], a[0], b + 2);
                mma16(d[t][1][nq * 2 + 1], a[1], b + 2);
            }
        }
    }
}

// ---------------------------------------------------------------------------
// layer A: x = conv(h)+cond+biases ; actsH = fp16(tanh(xa)*sigmoid(xb))
// CTA 128 tokens x 64 cols per half. grid (512, 4). K=1408 in 22 stages of 64.
// ---------------------------------------------------------------------------
__global__ void __launch_bounds__(256, 2) layerA_mma(
    const float* __restrict__ in_b, const float* __restrict__ cond_b,
    int layer, int dil) {
    extern __shared__ char smem[];
    const uint32_t sbase = smem_u32(smem);
    const int tid = threadIdx.x;
    const int lane = tid & 31;
    const int wid = tid >> 5;
    const int wm = wid & 3;
    const int wn = wid >> 2;
    const int row0 = blockIdx.x * 128;
    const int n0 = blockIdx.y * 64;
    const __half* __restrict__ wT = g_wA + (size_t)layer * 512 * 1408;

    {   // biases
        float* bsm = (float*)(smem + OFF_BIAS);
        bsm[tid] = in_b[layer * 512 + tid] + cond_b[layer * 512 + tid];
        bsm[256 + tid] = in_b[layer * 512 + 256 + tid] + cond_b[layer * 512 + 256 + tid];
    }

    auto load_stage = [&](int s, int buf) {
        const int kk0 = s * 64;
        const uint32_t abase = sbase + OFF_A(buf);
        const uint32_t bbase = sbase + OFF_B(buf);
        if (kk0 < 768) {
            const int tap = kk0 >> 8, kc = kk0 & 255;
            const int shift = (tap - 1) * dil;
            #pragma unroll
            for (int i = 0; i < 4; i++) {
                int v = tid + i * 256;
                int row = v >> 3, c8 = v & 7;
                int r = row0 + row;
                int ts = (r & (T_BATCH - 1)) + shift;
                const __half* src;
                uint32_t sz;
                if ((unsigned)ts < (unsigned)T_BATCH) {
                    src = g_hH + (size_t)(r + shift) * CH + kc + c8 * 8;
                    sz = 16;
                } else {
                    src = g_hH;
                    sz = 0;
                }
                CP16(abase + row * 144 + c8 * 16, src, sz);
            }
        } else {
            const int km = kk0 - 768;
            #pragma unroll
            for (int i = 0; i < 4; i++) {
                int v = tid + i * 256;
                int row = v >> 3, c8 = v & 7;
                const __half* src = g_spectH + (size_t)(row0 + row) * MEL + km + c8 * 8;
                CP16(abase + row * 144 + c8 * 16, src, 16);
            }
        }
        #pragma unroll
        for (int i = 0; i < 4; i++) {
            int v = tid + i * 256;
            int nl = v >> 3, c8 = v & 7;
            int ng = (nl < 64) ? (n0 + nl) : (n0 + 256 + nl - 64);
            const __half* src = wT + (size_t)ng * 1408 + kk0 + c8 * 8;
            CP16(bbase + nl * 144 + c8 * 16, src, 16);
        }
        CP_COMMIT();
    };

    float d[2][2][4][4] = {};

    load_stage(0, 0);
    for (int s = 0; s < 22; s++) {
        CP_WAIT(0);
        __syncthreads();
        if (s + 1 < 22) load_stage(s + 1, (s + 1) & 1);
        compute_f16(sbase + OFF_A(s & 1), sbase + OFF_B(s & 1), wm, wn, lane, d, 2);
    }

    __syncthreads();
    const float* bsm = (const float*)(smem + OFF_BIAS);
    const int ar = lane >> 2, ac = lane & 3;
    #pragma unroll
    for (int mi = 0; mi < 2; mi++) {
        #pragma unroll
        for (int eh = 0; eh < 2; eh++) {
            const int m = row0 + wm * 32 + mi * 16 + ar + eh * 8;
            #pragma unroll
            for (int ni = 0; ni < 4; ni++) {
                const int j = n0 + wn * 32 + ni * 8 + ac * 2;
                float xa0 = d[0][mi][ni][eh * 2 + 0] + bsm[j];
                float xa1 = d[0][mi][ni][eh * 2 + 1] + bsm[j + 1];
                float xb0 = d[1][mi][ni][eh * 2 + 0] + bsm[256 + j];
                float xb1 = d[1][mi][ni][eh * 2 + 1] + bsm[256 + j + 1];
                float o0 = tanhf(xa0) * (1.f / (1.f + expf(-xb0)));
                float o1 = tanhf(xa1) * (1.f / (1.f + expf(-xb1)));
                *(__half2*)&g_actsH[(size_t)m * CH + j] = __floats2half2_rn(o0, o1);
            }
        }
    }
}

// ---------------------------------------------------------------------------
// layer B: rs = acts@w + b ; h += rs[:,:256] (+fp16 shadow); skip += rs[:,256:]
// ---------------------------------------------------------------------------
__global__ void __launch_bounds__(256, 2) layerB_mma(
    const float* __restrict__ rs_b, int layer) {
    extern __shared__ char smem[];
    const uint32_t sbase = smem_u32(smem);
    const int tid = threadIdx.x;
    const int lane = tid & 31;
    const int wid = tid >> 5;
    const int wm = wid & 3;
    const int wn = wid >> 2;
    const int row0 = blockIdx.x * 128;
    const int n0 = blockIdx.y * 64;
    const __half* __restrict__ wT = g_wB + (size_t)layer * 512 * 256;

    {
        float* bsm = (float*)(smem + OFF_BIAS);
        bsm[tid] = rs_b[layer * 512 + tid];
        bsm[256 + tid] = rs_b[layer * 512 + 256 + tid];
    }

    auto load_stage = [&](int s, int buf) {
        const int kk0 = s * 64;
        const uint32_t abase = sbase + OFF_A(buf);
        const uint32_t bbase = sbase + OFF_B(buf);
        #pragma unroll
        for (int i = 0; i < 4; i++) {
            int v = tid + i * 256;
            int row = v >> 3, c8 = v & 7;
            const __half* src = g_actsH + (size_t)(row0 + row) * CH + kk0 + c8 * 8;
            CP16(abase + row * 144 + c8 * 16, src, 16);
        }
        #pragma unroll
        for (int i = 0; i < 4; i++) {
            int v = tid + i * 256;
            int nl = v >> 3, c8 = v & 7;
            int ng = (nl < 64) ? (n0 + nl) : (n0 + 256 + nl - 64);
            const __half* src = wT + (size_t)ng * 256 + kk0 + c8 * 8;
            CP16(bbase + nl * 144 + c8 * 16, src, 16);
        }
        CP_COMMIT();
    };

    float d[2][2][4][4] = {};

    load_stage(0, 0);
    for (int s = 0; s < 4; s++) {
        CP_WAIT(0);
        __syncthreads();
        if (s + 1 < 4) load_stage(s + 1, (s + 1) & 1);
        compute_f16(sbase + OFF_A(s & 1), sbase + OFF_B(s & 1), wm, wn, lane, d, 2);
    }

    __syncthreads();
    const float* bsm = (const float*)(smem + OFF_BIAS);
    const int ar = lane >> 2, ac = lane & 3;
    #pragma unroll
    for (int mi = 0; mi < 2; mi++) {
        #pragma unroll
        for (int eh = 0; eh < 2; eh++) {
            const int m = row0 + wm * 32 + mi * 16 + ar + eh * 8;
            #pragma unroll
            for (int ni = 0; ni < 4; ni++) {
                const int j = n0 + wn * 32 + ni * 8 + ac * 2;
                const size_t o = (size_t)m * CH + j;
                float2 hv = *(float2*)&g_h[o];
                float2 sv = *(float2*)&g_skip[o];
                hv.x += d[0][mi][ni][eh * 2 + 0] + bsm[j];
                hv.y += d[0][mi][ni][eh * 2 + 1] + bsm[j + 1];
                sv.x += d[1][mi][ni][eh * 2 + 0] + bsm[256 + j];
                sv.y += d[1][mi][ni][eh * 2 + 1] + bsm[256 + j + 1];
                *(float2*)&g_h[o] = hv;
                *(__half2*)&g_hH[o] = __floats2half2_rn(hv.x, hv.y);
                *(float2*)&g_skip[o] = sv;
            }
        }
    }
}

// ---------------------------------------------------------------------------
// last layer: skip += acts @ res_last_w + res_last_b (single half, B 64 rows)
// ---------------------------------------------------------------------------
__global__ void __launch_bounds__(256, 2) layerL_mma(const float* __restrict__ rl_b) {
    extern __shared__ char smem[];
    const uint32_t sbase = smem_u32(smem);
    const int tid = threadIdx.x;
    const int lane = tid & 31;
    const int wid = tid >> 5;
    const int wm = wid & 3;
    const int wn = wid >> 2;
    const int row0 = blockIdx.x * 128;
    const int n0 = blockIdx.y * 64;

    {
        float* bsm = (float*)(smem + OFFL_BIAS);
        bsm[tid] = rl_b[tid];
    }

    auto load_stage = [&](int s, int buf) {
        const int kk0 = s * 64;
        const uint32_t abase = sbase + OFFL_A(buf);
        const uint32_t bbase = sbase + OFFL_B(buf);
        #pragma unroll
        for (int i = 0; i < 4; i++) {
            int v = tid + i * 256;
            int row = v >> 3, c8 = v & 7;
            const __half* src = g_actsH + (size_t)(row0 + row) * CH + kk0 + c8 * 8;
            CP16(abase + row * 144 + c8 * 16, src, 16);
        }
        #pragma unroll
        for (int i = 0; i < 2; i++) {
            int v = tid + i * 256;
            int nl = v >> 3, c8 = v & 7;   // nl 0..63
            const __half* src = g_wL + (size_t)(n0 + nl) * 256 + kk0 + c8 * 8;
            CP16(bbase + nl * 144 + c8 * 16, src, 16);
        }
        CP_COMMIT();
    };

    float d[2][2][4][4] = {};

    load_stage(0, 0);
    for (int s = 0; s < 4; s++) {
        CP_WAIT(0);
        __syncthreads();
        if (s + 1 < 4) load_stage(s + 1, (s + 1) & 1);
        compute_f16(sbase + OFFL_A(s & 1), sbase + OFFL_B(s & 1), wm, wn, lane, d, 1);
    }

    __syncthreads();
    const float* bsm = (const float*)(smem + OFFL_BIAS);
    const int ar = lane >> 2, ac = lane & 3;
    #pragma unroll
    for (int mi = 0; mi < 2; mi++) {
        #pragma unroll
        for (int eh = 0; eh < 2; eh++) {
            const int m = row0 + wm * 32 + mi * 16 + ar + eh * 8;
            #pragma unroll
            for (int ni = 0; ni < 4; ni++) {
                const int j = n0 + wn * 32 + ni * 8 + ac * 2;
                const size_t o = (size_t)m * CH + j;
                float2 sv = *(float2*)&g_skip[o];
                sv.x += d[0][mi][ni][eh * 2 + 0] + bsm[j];
                sv.y += d[0][mi][ni][eh * 2 + 1] + bsm[j + 1];
                *(float2*)&g_skip[o] = sv;
            }
        }
    }
}

// ---------------------------------------------------------------------------
// end: out = skip @ end_w + end_b  — one thread per token, ew cached in smem
// ---------------------------------------------------------------------------
__global__ void end_kernel(const float* __restrict__ ew,
                           const float* __restrict__ eb,
                           float* __restrict__ out) {
    __shared__ float ews[2048];
    __shared__ float ebs[8];
    const int tid = threadIdx.x;
    #pragma unroll
    for (int i = 0; i < 8; i++) ews[tid + i * 256] = ew[tid + i * 256];
    if (tid < 8) ebs[tid] = eb[tid];
    __syncthreads();

    const int t = blockIdx.x * blockDim.x + tid;
    const float* s = &g_skip[(size_t)t * CH];
    float acc[8];
    #pragma unroll
    for (int o = 0; o < 8; o++) acc[o] = ebs[o];
    for (int c = 0; c < CH; c += 4) {
        float4 sv = *(const float4*)&s[c];
        #pragma unroll
        for (int e = 0; e < 4; e++) {
            float svv = (&sv.x)[e];
            const float* w = &ews[(c + e) * 8];
            #pragma unroll
            for (int o = 0; o < 8; o++) acc[o] += svv * w[o];
        }
    }
    float4* op = (float4*)&out[(size_t)t * 8];
    op[0] = make_float4(acc[0], acc[1], acc[2], acc[3]);
    op[1] = make_float4(acc[4], acc[5], acc[6], acc[7]);
}

// ---------------------------------------------------------------------------
extern "C" void kernel_launch(void* const* d_in, const int* in_sizes, int n_in,
                              void* d_out, int out_size) {
    const float* audio      = (const float*)d_in[0];
    const float* spect      = (const float*)d_in[1];
    const float* start_w    = (const float*)d_in[2];
    const float* start_b    = (const float*)d_in[3];
    const float* in_w       = (const float*)d_in[4];
    const float* in_b       = (const float*)d_in[5];
    const float* cond_w     = (const float*)d_in[6];
    const float* cond_b     = (const float*)d_in[7];
    const float* res_skip_w = (const float*)d_in[8];
    const float* res_skip_b = (const float*)d_in[9];
    const float* res_last_w = (const float*)d_in[10];
    const float* res_last_b = (const float*)d_in[11];
    const float* end_w      = (const float*)d_in[12];
    const float* end_b      = (const float*)d_in[13];
    float* out = (float*)d_out;

    cudaFuncSetAttribute(layerA_mma, cudaFuncAttributeMaxDynamicSharedMemorySize, SMEM_AB);
    cudaFuncSetAttribute(layerB_mma, cudaFuncAttributeMaxDynamicSharedMemorySize, SMEM_AB);
    cudaFuncSetAttribute(layerL_mma, cudaFuncAttributeMaxDynamicSharedMemorySize, SMEM_L);

    // launch order keeps layerA(l=0) in ncu's profiled slot (#4)
    prepW_kernel<<<(NA + NB + NL) / 256, 256>>>(in_w, cond_w, res_skip_w, res_last_w);
    start_kernel<<<(T_TOTAL * CH) / 256, 256>>>(audio, start_w, start_b);
    prepS_kernel<<<(T_TOTAL / 256) * MEL, 256>>>(spect);

    dim3 g4(512, 4);
    for (int l = 0; l < 8; l++) {
        layerA_mma<<<g4, 256, SMEM_AB>>>(in_b, cond_b, l, 1 << l);
        if (l < 7)
            layerB_mma<<<g4, 256, SMEM_AB>>>(res_skip_b, l);
        else
            layerL_mma<<<g4, 256, SMEM_L>>>(res_last_b);
    }

    end_kernel<<<T_TOTAL / 256, 256>>>(end_w, end_b, out);
}

// round 15
// speedup vs baseline: 1.0223x; 1.0223x over previous
#include <cuda_runtime.h>
#include <cuda_fp16.h>
#include <cstdint>
#include <math.h>

#define T_TOTAL 65536
#define T_BATCH 8192
#define CH 256
#define MEL 640

// ---------------- scratch (__device__ globals) ------------------------------
__device__ float  g_h[(size_t)T_TOTAL * CH];       // fp32 residual
__device__ float  g_skip[(size_t)T_TOTAL * CH];    // fp32 skip accumulator
__device__ __half g_hH[(size_t)T_TOTAL * CH];      // fp16 shadow of h
__device__ __half g_actsH[(size_t)T_TOTAL * CH];   // fp16 activations
__device__ __half g_spectH[(size_t)T_TOTAL * MEL]; // fp16 spect
__device__ __half g_wA[(size_t)8 * 512 * 1408];    // [layer][n][k]
__device__ __half g_wB[(size_t)7 * 512 * 256];     // [layer][n][k]
__device__ __half g_wL[(size_t)256 * 256];         // [n][k]

// ---------------- helpers ---------------------------------------------------
__device__ __forceinline__ uint32_t smem_u32(const void* p) {
    uint32_t a;
    asm("{ .reg .u64 t; cvta.to.shared.u64 t, %1; cvt.u32.u64 %0, t; }" : "=r"(a) : "l"(p));
    return a;
}

#define CP16(dst, src, sz) \
    asm volatile("cp.async.cg.shared.global [%0], [%1], 16, %2;" \
        :: "r"(dst), "l"(src), "r"(sz) : "memory")
#define CP_COMMIT() asm volatile("cp.async.commit_group;" ::: "memory")
#define CP_WAIT(n)  asm volatile("cp.async.wait_group %0;" :: "n"(n) : "memory")

__device__ __forceinline__ void mma16(float* d, const uint32_t* a, const uint32_t* b) {
    asm volatile(
        "mma.sync.aligned.m16n8k16.row.col.f32.f16.f16.f32 "
        "{%0,%1,%2,%3}, {%4,%5,%6,%7}, {%8,%9}, {%0,%1,%2,%3};"
        : "+f"(d[0]), "+f"(d[1]), "+f"(d[2]), "+f"(d[3])
        : "r"(a[0]), "r"(a[1]), "r"(a[2]), "r"(a[3]), "r"(b[0]), "r"(b[1]));
}

__device__ __forceinline__ void ldm4(uint32_t* r, uint32_t addr) {
    asm volatile("ldmatrix.sync.aligned.m8n8.x4.shared.b16 {%0,%1,%2,%3}, [%4];"
        : "=r"(r[0]), "=r"(r[1]), "=r"(r[2]), "=r"(r[3]) : "r"(addr));
}

#define HST 72   // smem row stride in halves (64 data + 8 pad = 144 B)

// ---- layerA/B layout: A 128 rows x 144B, B 128 rows x 144B -----------------
#define OFF_A(buf) ((buf) * 36864)
#define OFF_B(buf) (18432 + (buf) * 36864)
#define OFF_BIAS   73728
#define SMEM_AB    75776
// ---- layerL: A 128 rows, B 64 rows ------------------------------------------
#define OFFL_A(buf) ((buf) * 27648)
#define OFFL_B(buf) (18432 + (buf) * 27648)
#define OFFL_BIAS   55296
#define SMEM_L      56320

// ---------------------------------------------------------------------------
// prepW: all weights -> [n][k] fp16 (single launch)
// ---------------------------------------------------------------------------
#define NA (8u * 512u * 1408u)
#define NB (7u * 512u * 256u)
#define NL (256u * 256u)
__global__ void prepW_kernel(const float* __restrict__ in_w,
                             const float* __restrict__ cond_w,
                             const float* __restrict__ rsw,
                             const float* __restrict__ rlw) {
    uint32_t idx = blockIdx.x * blockDim.x + threadIdx.x;
    if (idx < NA) {
        int k = (int)(idx % 1408u);
        uint32_t t = idx / 1408u;
        int n = (int)(t & 511u);
        int l = (int)(t >> 9);
        float v;
        if (k < 768)
            v = in_w[(((size_t)l * 3 + (k >> 8)) * 256 + (k & 255)) * 512 + n];
        else
            v = cond_w[((size_t)l * 640 + (k - 768)) * 512 + n];
        g_wA[idx] = __float2half_rn(v);
    } else if (idx < NA + NB) {
        uint32_t r = idx - NA;
        int k = (int)(r & 255u);
        uint32_t t = r >> 8;
        int n = (int)(t & 511u);
        int l = (int)(t >> 9);
        g_wB[r] = __float2half_rn(rsw[((size_t)l * 256 + k) * 512 + n]);
    } else if (idx < NA + NB + NL) {
        uint32_t r = idx - NA - NB;
        int k = (int)(r & 255u);
        int n = (int)(r >> 8);
        g_wL[r] = __float2half_rn(rlw[k * 256 + n]);
    }
}

// ---------------------------------------------------------------------------
// start: h = audio @ start_w + start_b ; hH = fp16(h); skip = 0
// ---------------------------------------------------------------------------
__global__ void start_kernel(const float* __restrict__ audio,
                             const float* __restrict__ sw,
                             const float* __restrict__ sb) {
    int idx = blockIdx.x * blockDim.x + threadIdx.x;
    int t = idx >> 8;
    int c = idx & 255;
    float4 a = *(const float4*)&audio[(size_t)t * 4];
    float v = sb[c] + a.x * sw[c] + a.y * sw[256 + c] + a.z * sw[512 + c] + a.w * sw[768 + c];
    g_h[idx] = v;
    g_hH[idx] = __float2half_rn(v);
    g_skip[idx] = 0.f;
}

__global__ void prepS_kernel(const float* __restrict__ spect) {
    size_t idx = (size_t)blockIdx.x * blockDim.x + threadIdx.x;
    g_spectH[idx] = __float2half_rn(spect[idx]);
}

// ---------------------------------------------------------------------------
// 64x64 warp-tile compute via ldmatrix. 4 warps/CTA: wm=wid&1, wn=wid>>1.
// A rows wm*64..+64 ; B rows wn*64..+64 ; d[4][8][4] (128 accums).
// B tile rows are 8-row blocks alternating gate halves (see load_stage).
// ---------------------------------------------------------------------------
__device__ __forceinline__ void compute_w64(uint32_t abuf, uint32_t bbuf,
                                            int wm, int wn, int lane,
                                            float d[4][8][4]) {
    const uint32_t a_off = abuf + ((wm * 64 + (lane & 15)) * HST + (lane >> 4) * 8) * 2;
    const uint32_t b_off = bbuf + ((wn * 64 + (lane & 7) + (lane >> 4) * 8) * HST
                                   + ((lane >> 3) & 1) * 8) * 2;
    #pragma unroll
    for (int q = 0; q < 4; q++) {
        uint32_t a[4][4];
        #pragma unroll
        for (int mi = 0; mi < 4; mi++)
            ldm4(a[mi], a_off + mi * 16 * HST * 2 + q * 32);
        #pragma unroll
        for (int nb = 0; nb < 4; nb++) {
            uint32_t b[4];
            ldm4(b, b_off + nb * 16 * HST * 2 + q * 32);
            #pragma unroll
            for (int mi = 0; mi < 4; mi++) {
                mma16(d[mi][nb * 2],     a[mi], b);
                mma16(d[mi][nb * 2 + 1], a[mi], b + 2);
            }
        }
    }
}

// 64x32 variant for layerL (B tile 64 rows): d[4][4][4]
__device__ __forceinline__ void compute_w64L(uint32_t abuf, uint32_t bbuf,
                                             int wm, int wn, int lane,
                                             float d[4][4][4]) {
    const uint32_t a_off = abuf + ((wm * 64 + (lane & 15)) * HST + (lane >> 4) * 8) * 2;
    const uint32_t b_off = bbuf + ((wn * 32 + (lane & 7) + (lane >> 4) * 8) * HST
                                   + ((lane >> 3) & 1) * 8) * 2;
    #pragma unroll
    for (int q = 0; q < 4; q++) {
        uint32_t a[4][4];
        #pragma unroll
        for (int mi = 0; mi < 4; mi++)
            ldm4(a[mi], a_off + mi * 16 * HST * 2 + q * 32);
        #pragma unroll
        for (int nb = 0; nb < 2; nb++) {
            uint32_t b[4];
            ldm4(b, b_off + nb * 16 * HST * 2 + q * 32);
            #pragma unroll
            for (int mi = 0; mi < 4; mi++) {
                mma16(d[mi][nb * 2],     a[mi], b);
                mma16(d[mi][nb * 2 + 1], a[mi], b + 2);
            }
        }
    }
}

// ---------------------------------------------------------------------------
// layer A: x = conv(h)+cond+biases ; actsH = fp16(tanh(xa)*sigmoid(xb))
// CTA 128 tokens x 64 act cols (128 B-rows, halves interleaved by 8-row blocks)
// 128 threads. grid (512, 4). K=1408 in 22 stages of 64.
// ---------------------------------------------------------------------------
__global__ void __launch_bounds__(128, 2) layerA_mma(
    const float* __restrict__ in_b, const float* __restrict__ cond_b,
    int layer, int dil) {
    extern __shared__ char smem[];
    const uint32_t sbase = smem_u32(smem);
    const int tid = threadIdx.x;
    const int lane = tid & 31;
    const int wid = tid >> 5;
    const int wm = wid & 1;
    const int wn = wid >> 1;
    const int row0 = blockIdx.x * 128;
    const int n0 = blockIdx.y * 64;
    const __half* __restrict__ wT = g_wA + (size_t)layer * 512 * 1408;

    {   // biases (512 floats, 128 threads)
        float* bsm = (float*)(smem + OFF_BIAS);
        #pragma unroll
        for (int i = 0; i < 4; i++) {
            int c = tid + i * 128;
            bsm[c] = in_b[layer * 512 + c] + cond_b[layer * 512 + c];
        }
    }

    auto load_stage = [&](int s, int buf) {
        const int kk0 = s * 64;
        const uint32_t abase = sbase + OFF_A(buf);
        const uint32_t bbase = sbase + OFF_B(buf);
        if (kk0 < 768) {
            const int tap = kk0 >> 8, kc = kk0 & 255;
            const int shift = (tap - 1) * dil;
            #pragma unroll
            for (int i = 0; i < 8; i++) {
                int v = tid + i * 128;
                int row = v >> 3, c8 = v & 7;
                int r = row0 + row;
                int ts = (r & (T_BATCH - 1)) + shift;
                const __half* src;
                uint32_t sz;
                if ((unsigned)ts < (unsigned)T_BATCH) {
                    src = g_hH + (size_t)(r + shift) * CH + kc + c8 * 8;
                    sz = 16;
                } else {
                    src = g_hH;
                    sz = 0;
                }
                CP16(abase + row * 144 + c8 * 16, src, sz);
            }
        } else {
            const int km = kk0 - 768;
            #pragma unroll
            for (int i = 0; i < 8; i++) {
                int v = tid + i * 128;
                int row = v >> 3, c8 = v & 7;
                const __half* src = g_spectH + (size_t)(row0 + row) * MEL + km + c8 * 8;
                CP16(abase + row * 144 + c8 * 16, src, 16);
            }
        }
        // B rows: blk = nl>>3 ; half = blk&1 ; colblk = blk>>1
        #pragma unroll
        for (int i = 0; i < 8; i++) {
            int v = tid + i * 128;
            int nl = v >> 3, c8 = v & 7;
            int blk = nl >> 3, within = nl & 7;
            int ng = n0 + (blk >> 1) * 8 + within + (blk & 1) * 256;
            const __half* src = wT + (size_t)ng * 1408 + kk0 + c8 * 8;
            CP16(bbase + nl * 144 + c8 * 16, src, 16);
        }
        CP_COMMIT();
    };

    float d[4][8][4] = {};

    load_stage(0, 0);
    for (int s = 0; s < 22; s++) {
        CP_WAIT(0);
        __syncthreads();
        if (s + 1 < 22) load_stage(s + 1, (s + 1) & 1);
        compute_w64(sbase + OFF_A(s & 1), sbase + OFF_B(s & 1), wm, wn, lane, d);
    }

    __syncthreads();
    const float* bsm = (const float*)(smem + OFF_BIAS);
    const int ar = lane >> 2, ac = lane & 3;
    #pragma unroll
    for (int mi = 0; mi < 4; mi++) {
        #pragma unroll
        for (int eh = 0; eh < 2; eh++) {
            const int m = row0 + wm * 64 + mi * 16 + ar + eh * 8;
            #pragma unroll
            for (int cb = 0; cb < 4; cb++) {
                const int j = n0 + (wn * 4 + cb) * 8 + ac * 2;
                float xa0 = d[mi][cb * 2][eh * 2 + 0] + bsm[j];
                float xa1 = d[mi][cb * 2][eh * 2 + 1] + bsm[j + 1];
                float xb0 = d[mi][cb * 2 + 1][eh * 2 + 0] + bsm[256 + j];
                float xb1 = d[mi][cb * 2 + 1][eh * 2 + 1] + bsm[256 + j + 1];
                float o0 = tanhf(xa0) * (1.f / (1.f + expf(-xb0)));
                float o1 = tanhf(xa1) * (1.f / (1.f + expf(-xb1)));
                *(__half2*)&g_actsH[(size_t)m * CH + j] = __floats2half2_rn(o0, o1);
            }
        }
    }
}

// ---------------------------------------------------------------------------
// layer B: rs = acts@w + b ; h += rs[:,:256] (+fp16 shadow); skip += rs[:,256:]
// ---------------------------------------------------------------------------
__global__ void __launch_bounds__(128, 2) layerB_mma(
    const float* __restrict__ rs_b, int layer) {
    extern __shared__ char smem[];
    const uint32_t sbase = smem_u32(smem);
    const int tid = threadIdx.x;
    const int lane = tid & 31;
    const int wid = tid >> 5;
    const int wm = wid & 1;
    const int wn = wid >> 1;
    const int row0 = blockIdx.x * 128;
    const int n0 = blockIdx.y * 64;
    const __half* __restrict__ wT = g_wB + (size_t)layer * 512 * 256;

    {
        float* bsm = (float*)(smem + OFF_BIAS);
        #pragma unroll
        for (int i = 0; i < 4; i++) {
            int c = tid + i * 128;
            bsm[c] = rs_b[layer * 512 + c];
        }
    }

    auto load_stage = [&](int s, int buf) {
        const int kk0 = s * 64;
        const uint32_t abase = sbase + OFF_A(buf);
        const uint32_t bbase = sbase + OFF_B(buf);
        #pragma unroll
        for (int i = 0; i < 8; i++) {
            int v = tid + i * 128;
            int row = v >> 3, c8 = v & 7;
            const __half* src = g_actsH + (size_t)(row0 + row) * CH + kk0 + c8 * 8;
            CP16(abase + row * 144 + c8 * 16, src, 16);
        }
        #pragma unroll
        for (int i = 0; i < 8; i++) {
            int v = tid + i * 128;
            int nl = v >> 3, c8 = v & 7;
            int blk = nl >> 3, within = nl & 7;
            int ng = n0 + (blk >> 1) * 8 + within + (blk & 1) * 256;
            const __half* src = wT + (size_t)ng * 256 + kk0 + c8 * 8;
            CP16(bbase + nl * 144 + c8 * 16, src, 16);
        }
        CP_COMMIT();
    };

    float d[4][8][4] = {};

    load_stage(0, 0);
    for (int s = 0; s < 4; s++) {
        CP_WAIT(0);
        __syncthreads();
        if (s + 1 < 4) load_stage(s + 1, (s + 1) & 1);
        compute_w64(sbase + OFF_A(s & 1), sbase + OFF_B(s & 1), wm, wn, lane, d);
    }

    __syncthreads();
    const float* bsm = (const float*)(smem + OFF_BIAS);
    const int ar = lane >> 2, ac = lane & 3;
    #pragma unroll
    for (int mi = 0; mi < 4; mi++) {
        #pragma unroll
        for (int eh = 0; eh < 2; eh++) {
            const int m = row0 + wm * 64 + mi * 16 + ar + eh * 8;
            #pragma unroll
            for (int cb = 0; cb < 4; cb++) {
                const int j = n0 + (wn * 4 + cb) * 8 + ac * 2;
                const size_t o = (size_t)m * CH + j;
                float2 hv = *(float2*)&g_h[o];
                float2 sv = *(float2*)&g_skip[o];
                hv.x += d[mi][cb * 2][eh * 2 + 0] + bsm[j];
                hv.y += d[mi][cb * 2][eh * 2 + 1] + bsm[j + 1];
                sv.x += d[mi][cb * 2 + 1][eh * 2 + 0] + bsm[256 + j];
                sv.y += d[mi][cb * 2 + 1][eh * 2 + 1] + bsm[256 + j + 1];
                *(float2*)&g_h[o] = hv;
                *(__half2*)&g_hH[o] = __floats2half2_rn(hv.x, hv.y);
                *(float2*)&g_skip[o] = sv;
            }
        }
    }
}

// ---------------------------------------------------------------------------
// last layer: skip += acts @ res_last_w + res_last_b (B tile 64 rows, no halves)
// ---------------------------------------------------------------------------
__global__ void __launch_bounds__(128, 2) layerL_mma(const float* __restrict__ rl_b) {
    extern __shared__ char smem[];
    const uint32_t sbase = smem_u32(smem);
    const int tid = threadIdx.x;
    const int lane = tid & 31;
    const int wid = tid >> 5;
    const int wm = wid & 1;
    const int wn = wid >> 1;
    const int row0 = blockIdx.x * 128;
    const int n0 = blockIdx.y * 64;

    {
        float* bsm = (float*)(smem + OFFL_BIAS);
        bsm[tid] = rl_b[tid];
        bsm[128 + tid] = rl_b[128 + tid];
    }

    auto load_stage = [&](int s, int buf) {
        const int kk0 = s * 64;
        const uint32_t abase = sbase + OFFL_A(buf);
        const uint32_t bbase = sbase + OFFL_B(buf);
        #pragma unroll
        for (int i = 0; i < 8; i++) {
            int v = tid + i * 128;
            int row = v >> 3, c8 = v & 7;
            const __half* src = g_actsH + (size_t)(row0 + row) * CH + kk0 + c8 * 8;
            CP16(abase + row * 144 + c8 * 16, src, 16);
        }
        #pragma unroll
        for (int i = 0; i < 4; i++) {
            int v = tid + i * 128;
            int nl = v >> 3, c8 = v & 7;   // nl 0..63
            const __half* src = g_wL + (size_t)(n0 + nl) * 256 + kk0 + c8 * 8;
            CP16(bbase + nl * 144 + c8 * 16, src, 16);
        }
        CP_COMMIT();
    };

    float d[4][4][4] = {};

    load_stage(0, 0);
    for (int s = 0; s < 4; s++) {
        CP_WAIT(0);
        __syncthreads();
        if (s + 1 < 4) load_stage(s + 1, (s + 1) & 1);
        compute_w64L(sbase + OFFL_A(s & 1), sbase + OFFL_B(s & 1), wm, wn, lane, d);
    }

    __syncthreads();
    const float* bsm = (const float*)(smem + OFFL_BIAS);
    const int ar = lane >> 2, ac = lane & 3;
    #pragma unroll
    for (int mi = 0; mi < 4; mi++) {
        #pragma unroll
        for (int eh = 0; eh < 2; eh++) {
            const int m = row0 + wm * 64 + mi * 16 + ar + eh * 8;
            #pragma unroll
            for (int nj = 0; nj < 4; nj++) {
                const int j = n0 + wn * 32 + nj * 8 + ac * 2;
                const size_t o = (size_t)m * CH + j;
                float2 sv = *(float2*)&g_skip[o];
                sv.x += d[mi][nj][eh * 2 + 0] + bsm[j];
                sv.y += d[mi][nj][eh * 2 + 1] + bsm[j + 1];
                *(float2*)&g_skip[o] = sv;
            }
        }
    }
}

// ---------------------------------------------------------------------------
// end: out = skip @ end_w + end_b  — one thread per token, ew cached in smem
// ---------------------------------------------------------------------------
__global__ void end_kernel(const float* __restrict__ ew,
                           const float* __restrict__ eb,
                           float* __restrict__ out) {
    __shared__ float ews[2048];
    __shared__ float ebs[8];
    const int tid = threadIdx.x;
    #pragma unroll
    for (int i = 0; i < 8; i++) ews[tid + i * 256] = ew[tid + i * 256];
    if (tid < 8) ebs[tid] = eb[tid];
    __syncthreads();

    const int t = blockIdx.x * blockDim.x + tid;
    const float* s = &g_skip[(size_t)t * CH];
    float acc[8];
    #pragma unroll
    for (int o = 0; o < 8; o++) acc[o] = ebs[o];
    for (int c = 0; c < CH; c += 4) {
        float4 sv = *(const float4*)&s[c];
        #pragma unroll
        for (int e = 0; e < 4; e++) {
            float svv = (&sv.x)[e];
            const float* w = &ews[(c + e) * 8];
            #pragma unroll
            for (int o = 0; o < 8; o++) acc[o] += svv * w[o];
        }
    }
    float4* op = (float4*)&out[(size_t)t * 8];
    op[0] = make_float4(acc[0], acc[1], acc[2], acc[3]);
    op[1] = make_float4(acc[4], acc[5], acc[6], acc[7]);
}

// ---------------------------------------------------------------------------
extern "C" void kernel_launch(void* const* d_in, const int* in_sizes, int n_in,
                              void* d_out, int out_size) {
    const float* audio      = (const float*)d_in[0];
    const float* spect      = (const float*)d_in[1];
    const float* start_w    = (const float*)d_in[2];
    const float* start_b    = (const float*)d_in[3];
    const float* in_w       = (const float*)d_in[4];
    const float* in_b       = (const float*)d_in[5];
    const float* cond_w     = (const float*)d_in[6];
    const float* cond_b     = (const float*)d_in[7];
    const float* res_skip_w = (const float*)d_in[8];
    const float* res_skip_b = (const float*)d_in[9];
    const float* res_last_w = (const float*)d_in[10];
    const float* res_last_b = (const float*)d_in[11];
    const float* end_w      = (const float*)d_in[12];
    const float* end_b      = (const float*)d_in[13];
    float* out = (float*)d_out;

    cudaFuncSetAttribute(layerA_mma, cudaFuncAttributeMaxDynamicSharedMemorySize, SMEM_AB);
    cudaFuncSetAttribute(layerB_mma, cudaFuncAttributeMaxDynamicSharedMemorySize, SMEM_AB);
    cudaFuncSetAttribute(layerL_mma, cudaFuncAttributeMaxDynamicSharedMemorySize, SMEM_L);

    // launch order keeps layerA(l=0) in ncu's profiled slot (#4)
    prepW_kernel<<<(NA + NB + NL) / 256, 256>>>(in_w, cond_w, res_skip_w, res_last_w);
    start_kernel<<<(T_TOTAL * CH) / 256, 256>>>(audio, start_w, start_b);
    prepS_kernel<<<(T_TOTAL / 256) * MEL, 256>>>(spect);

    dim3 g4(512, 4);
    for (int l = 0; l < 8; l++) {
        layerA_mma<<<g4, 128, SMEM_AB>>>(in_b, cond_b, l, 1 << l);
        if (l < 7)
            layerB_mma<<<g4, 128, SMEM_AB>>>(res_skip_b, l);
        else
            layerL_mma<<<g4, 128, SMEM_L>>>(res_last_b);
    }

    end_kernel<<<T_TOTAL / 256, 256>>>(end_w, end_b, out);
}